// round 5
// baseline (speedup 1.0000x reference)
#include <cuda_runtime.h>
#include <cstdint>

// Skeleton FK: angles [B,24,6] f32, xyz [1,24,3] f32 -> out [B,24,3] f32
//
// 4 warps/block, warp = role, lane = batch row (32 rows/CTA).
//   A: root(store) + 1,4,7,10 ; re-root + 2,5,8,11
//   B: root + 3,6,9 (store) + 12,15
//   C: root + 3,6,9 + 13,16,18,20,22
//   D: root + 3,6,9 + 14,17,19,21,23
//
// smem layout per row (RROW=212 floats = 848B = 53*16B, odd multiple of 16
// -> conflict-free LDS.128 across lanes):
//   [c*8 .. c*8+5]   : joint c angles (padded to 8 floats)  -- later
//                      overwritten in place by T_c (joints not shared)
//   [192+(c/3)*4]    : side T slots for shared joints {0,3,6,9}
// xoff padded to 4 floats/joint -> single broadcast LDS.128 per joint.

#define TPB  128
#define ROWS 32
#define RROW 212
#define SIDE 192
#define XOFF_SZ 104   // 24*4 + 8 pad (keeps rows 16B-aligned)

__constant__ int c_parent[24] = {-1, 0, 0, 0, 1, 2, 3, 4, 5, 6, 7, 8,
                                  9, 9, 9, 12, 13, 14, 16, 17, 18, 19, 20, 21};

// T-slot base (in floats) for joint c; folds to a constant when c is literal.
__device__ __forceinline__ int tslot(int c) {
    return (c <= 9 && (c % 3) == 0) ? (SIDE + (c / 3) * 4) : (c * 8);
}

// rot6d from a padded 8-float joint slot (16B-aligned): LDS.128 + LDS.64.
__device__ __forceinline__ void rot6d_p(const float* __restrict__ sl, float R[9]) {
    float4 a = *reinterpret_cast<const float4*>(sl);      // a1x a1y a1z a2x
    float2 b = *reinterpret_cast<const float2*>(sl + 4);  // a2y a2z
    float a1x = a.x, a1y = a.y, a1z = a.z;
    float a2x = a.w, a2y = b.x, a2z = b.y;
    float inv1 = rsqrtf(fmaf(a1x, a1x, fmaf(a1y, a1y, a1z * a1z)));
    float b1x = a1x * inv1, b1y = a1y * inv1, b1z = a1z * inv1;
    float d = fmaf(b1x, a2x, fmaf(b1y, a2y, b1z * a2z));
    float c2x = fmaf(-d, b1x, a2x);
    float c2y = fmaf(-d, b1y, a2y);
    float c2z = fmaf(-d, b1z, a2z);
    float inv2 = rsqrtf(fmaf(c2x, c2x, fmaf(c2y, c2y, c2z * c2z)));
    float b2x = c2x * inv2, b2y = c2y * inv2, b2z = c2z * inv2;
    float b3x = fmaf(b1y, b2z, -b1z * b2y);
    float b3y = fmaf(b1z, b2x, -b1x * b2z);
    float b3z = fmaf(b1x, b2y, -b1y * b2x);
    R[0] = b1x; R[1] = b1y; R[2] = b1z;
    R[3] = b2x; R[4] = b2y; R[5] = b2z;
    R[6] = b3x; R[7] = b3y; R[8] = b3z;
}

// Root: R = rot6d(slot 0), T = R @ xyz0; store -> side slot (STS.128).
__device__ __forceinline__ void fk_root(float* __restrict__ srow,
                                        const float* __restrict__ xoff,
                                        float R[9], float T[3], bool store) {
    rot6d_p(srow, R);
    float4 o = *reinterpret_cast<const float4*>(xoff);
    T[0] = fmaf(R[0], o.x, fmaf(R[1], o.y, R[2] * o.z));
    T[1] = fmaf(R[3], o.x, fmaf(R[4], o.y, R[5] * o.z));
    T[2] = fmaf(R[6], o.x, fmaf(R[7], o.y, R[8] * o.z));
    if (store)
        *reinterpret_cast<float4*>(srow + SIDE) = make_float4(T[0], T[1], T[2], T[2]);
}

// One FK step for child joint c (c is a compile-time literal at call sites).
__device__ __forceinline__ void fk_step(float* __restrict__ srow,
                                        const float* __restrict__ xoff,
                                        int c, float R[9], float T[3],
                                        bool store) {
    float rc[9];
    rot6d_p(srow + c * 8, rc);
    float4 o = *reinterpret_cast<const float4*>(xoff + c * 4);
    float t3x = fmaf(rc[0], o.x, fmaf(rc[1], o.y, rc[2] * o.z));
    float t3y = fmaf(rc[3], o.x, fmaf(rc[4], o.y, rc[5] * o.z));
    float t3z = fmaf(rc[6], o.x, fmaf(rc[7], o.y, rc[8] * o.z));
    float Tn0 = fmaf(R[0], t3x, fmaf(R[1], t3y, fmaf(R[2], t3z, T[0])));
    float Tn1 = fmaf(R[3], t3x, fmaf(R[4], t3y, fmaf(R[5], t3z, T[1])));
    float Tn2 = fmaf(R[6], t3x, fmaf(R[7], t3y, fmaf(R[8], t3z, T[2])));
    float Rn[9];
#pragma unroll
    for (int r = 0; r < 3; r++)
#pragma unroll
        for (int k = 0; k < 3; k++)
            Rn[r * 3 + k] = fmaf(R[r * 3 + 0], rc[k],
                            fmaf(R[r * 3 + 1], rc[3 + k],
                                 R[r * 3 + 2] * rc[6 + k]));
#pragma unroll
    for (int i = 0; i < 9; i++) R[i] = Rn[i];
    T[0] = Tn0; T[1] = Tn1; T[2] = Tn2;
    if (store)
        *reinterpret_cast<float4*>(srow + tslot(c)) =
            make_float4(Tn0, Tn1, Tn2, Tn2);
}

__global__ __launch_bounds__(TPB, 8) void skeleton_fk_kernel(
    const float* __restrict__ angles,
    const float* __restrict__ xyz,
    float* __restrict__ out,
    int B)
{
    __shared__ __align__(16) float sm[XOFF_SZ + ROWS * RROW];
    float* xoff = sm;            // [24][4] padded bone offsets
    float* rows = sm + XOFF_SZ;  // [32][212]

    const int t    = threadIdx.x;
    const int wid  = t >> 5;
    const int lane = t & 31;
    const int b0   = blockIdx.x * ROWS;
    const int nvalid = min(ROWS, B - b0);

    // ---- bone offsets (padded to float4; root slot = absolute root pos) ----
    if (t < 24) {
        int p = c_parent[t];
        float x = __ldg(xyz + t * 3 + 0);
        float y = __ldg(xyz + t * 3 + 1);
        float z = __ldg(xyz + t * 3 + 2);
        if (p >= 0) {
            x -= __ldg(xyz + p * 3 + 0);
            y -= __ldg(xyz + p * 3 + 1);
            z -= __ldg(xyz + p * 3 + 2);
        }
        *reinterpret_cast<float4*>(xoff + t * 4) = make_float4(x, y, z, 0.0f);
    }

    // ---- phase 1: coalesced LDG.128, stage into padded slots (2x STS.64) ----
    {
        const float4* __restrict__ g4 =
            reinterpret_cast<const float4*>(angles) + (size_t)b0 * 36;
        const int total4 = nvalid * 36;
#pragma unroll
        for (int it = 0; it < 9; it++) {
            int idx = it * TPB + t;
            if (idx < total4) {
                float4 v = g4[idx];
                int row = idx / 36;
                int c4  = idx % 36;
                int f0  = 4 * c4;          // even, 0..140
                int j0  = f0 / 6, p0 = f0 - 6 * j0;
                int f1  = f0 + 2;
                int j1  = f1 / 6, p1 = f1 - 6 * j1;
                float* rb = rows + row * RROW;
                *reinterpret_cast<float2*>(rb + j0 * 8 + p0) = make_float2(v.x, v.y);
                *reinterpret_cast<float2*>(rb + j1 * 8 + p1) = make_float2(v.z, v.w);
            }
        }
    }
    __syncthreads();

    // ---- phase 2: lane -> row, warp -> role ----
    if (lane < nvalid) {
        float* srow = rows + lane * RROW;
        float R[9], T[3];

        if (wid == 0) {            // role A
            fk_root(srow, xoff, R, T, true);
            fk_step(srow, xoff, 1,  R, T, true);
            fk_step(srow, xoff, 4,  R, T, true);
            fk_step(srow, xoff, 7,  R, T, true);
            fk_step(srow, xoff, 10, R, T, true);
            fk_root(srow, xoff, R, T, false);
            fk_step(srow, xoff, 2,  R, T, true);
            fk_step(srow, xoff, 5,  R, T, true);
            fk_step(srow, xoff, 8,  R, T, true);
            fk_step(srow, xoff, 11, R, T, true);
        } else if (wid == 1) {     // role B
            fk_root(srow, xoff, R, T, false);
            fk_step(srow, xoff, 3,  R, T, true);
            fk_step(srow, xoff, 6,  R, T, true);
            fk_step(srow, xoff, 9,  R, T, true);
            fk_step(srow, xoff, 12, R, T, true);
            fk_step(srow, xoff, 15, R, T, true);
        } else if (wid == 2) {     // role C
            fk_root(srow, xoff, R, T, false);
            fk_step(srow, xoff, 3,  R, T, false);
            fk_step(srow, xoff, 6,  R, T, false);
            fk_step(srow, xoff, 9,  R, T, false);
            fk_step(srow, xoff, 13, R, T, true);
            fk_step(srow, xoff, 16, R, T, true);
            fk_step(srow, xoff, 18, R, T, true);
            fk_step(srow, xoff, 20, R, T, true);
            fk_step(srow, xoff, 22, R, T, true);
        } else {                   // role D
            fk_root(srow, xoff, R, T, false);
            fk_step(srow, xoff, 3,  R, T, false);
            fk_step(srow, xoff, 6,  R, T, false);
            fk_step(srow, xoff, 9,  R, T, false);
            fk_step(srow, xoff, 14, R, T, true);
            fk_step(srow, xoff, 17, R, T, true);
            fk_step(srow, xoff, 19, R, T, true);
            fk_step(srow, xoff, 21, R, T, true);
            fk_step(srow, xoff, 23, R, T, true);
        }
    }
    __syncthreads();

    // ---- phase 3: gather via 2x LDS.128 + component selects, STG.128 ----
    // Output float4 idx: row = idx/18, m = idx%18, s = m/3, pat = m%3.
    //   pat0: {A0,A1,A2,B0}  A=joint(4s)
    //   pat1: {A1,A2,B0,B1}  A=joint(4s+1)
    //   pat2: {A2,B0,B1,B2}  A=joint(4s+2)      B = A+1 always.
    {
        float4* __restrict__ o4 =
            reinterpret_cast<float4*>(out) + (size_t)b0 * 18;
        const int total4 = nvalid * 18;
#pragma unroll
        for (int it = 0; it < 5; it++) {
            int idx = it * TPB + t;
            if (idx < total4) {
                int row = idx / 18;
                int m   = idx % 18;
                int s   = m / 3;
                int pat = m - 3 * s;
                int cA  = 4 * s + ((pat == 0) ? 0 : (pat == 1) ? 1 : 2);
                const float* rb = rows + row * RROW;
                float4 A  = *reinterpret_cast<const float4*>(rb + tslot(cA));
                float4 Bv = *reinterpret_cast<const float4*>(rb + tslot(cA + 1));
                float4 v;
                v.x = (pat == 0) ? A.x : (pat == 1) ? A.y : A.z;
                v.y = (pat == 0) ? A.y : (pat == 1) ? A.z : Bv.x;
                v.z = (pat == 0) ? A.z : (pat == 1) ? Bv.x : Bv.y;
                v.w = (pat == 0) ? Bv.x : (pat == 1) ? Bv.y : Bv.z;
                o4[idx] = v;
            }
        }
    }
}

extern "C" void kernel_launch(void* const* d_in, const int* in_sizes, int n_in,
                              void* d_out, int out_size) {
    const float* angles = (const float*)d_in[0];
    const float* xyz    = (const float*)d_in[1];
    float* out          = (float*)d_out;
    const int B = in_sizes[0] / (24 * 6);
    const int blocks = (B + ROWS - 1) / ROWS;
    skeleton_fk_kernel<<<blocks, TPB>>>(angles, xyz, out, B);
}